// round 9
// baseline (speedup 1.0000x reference)
#include <cuda_runtime.h>
#include <cuda_bf16.h>
#include <math.h>
#include <stdint.h>

// ---------------------------------------------------------------------------
// Problem constants (Qwen3.5 MoE GatedDeltaNet, T=4096)
// ---------------------------------------------------------------------------
#define T_TOKENS   4096
#define HIDDEN     2048
#define NUM_K_HEADS 16
#define NUM_V_HEADS 32
#define DK         128
#define DV         128
#define KEY_DIM    (NUM_K_HEADS * DK)          // 2048
#define VALUE_DIM  (NUM_V_HEADS * DV)          // 4096
#define QKV_DIM    (2 * KEY_DIM + VALUE_DIM)   // 8192
#define KCONV      4

// ---------------------------------------------------------------------------
// Scratch (device globals; no allocations allowed)
// ---------------------------------------------------------------------------
__device__ float g_mixed[(size_t)T_TOKENS * QKV_DIM];
__device__ float g_x[(size_t)T_TOKENS * QKV_DIM];
__device__ float g_z[(size_t)T_TOKENS * VALUE_DIM];
__device__ float g_beta[(size_t)T_TOKENS * NUM_V_HEADS];
__device__ float g_expg[(size_t)T_TOKENS * NUM_V_HEADS];
__device__ float g_o[(size_t)T_TOKENS * VALUE_DIM];

// bf16 hi/lo split operands for tensor-core GEMMs
__device__ __nv_bfloat16 g_Hhi[(size_t)T_TOKENS * HIDDEN];
__device__ __nv_bfloat16 g_Hlo[(size_t)T_TOKENS * HIDDEN];
__device__ __nv_bfloat16 g_W1hi[(size_t)QKV_DIM * HIDDEN];
__device__ __nv_bfloat16 g_W1lo[(size_t)QKV_DIM * HIDDEN];
__device__ __nv_bfloat16 g_W2hi[(size_t)VALUE_DIM * HIDDEN];
__device__ __nv_bfloat16 g_W2lo[(size_t)VALUE_DIM * HIDDEN];
__device__ __nv_bfloat16 g_W3hi[(size_t)HIDDEN * VALUE_DIM];
__device__ __nv_bfloat16 g_W3lo[(size_t)HIDDEN * VALUE_DIM];
__device__ __nv_bfloat16 g_Ohi[(size_t)T_TOKENS * VALUE_DIM];
__device__ __nv_bfloat16 g_Olo[(size_t)T_TOKENS * VALUE_DIM];

// ---------------------------------------------------------------------------
// fp32 -> bf16 hi/lo split (elementwise)
// ---------------------------------------------------------------------------
__global__ __launch_bounds__(256) void split_f32_kernel(const float* __restrict__ src,
                                                        __nv_bfloat16* __restrict__ hi,
                                                        __nv_bfloat16* __restrict__ lo,
                                                        int n4) {
    int i = blockIdx.x * blockDim.x + threadIdx.x;
    if (i >= n4) return;
    float4 v = reinterpret_cast<const float4*>(src)[i];
    __nv_bfloat16 hx = __float2bfloat16_rn(v.x);
    __nv_bfloat16 hy = __float2bfloat16_rn(v.y);
    __nv_bfloat16 hz = __float2bfloat16_rn(v.z);
    __nv_bfloat16 hw = __float2bfloat16_rn(v.w);
    __nv_bfloat162 h01; h01.x = hx; h01.y = hy;
    __nv_bfloat162 h23; h23.x = hz; h23.y = hw;
    __nv_bfloat162 l01, l23;
    l01.x = __float2bfloat16_rn(v.x - __bfloat162float(hx));
    l01.y = __float2bfloat16_rn(v.y - __bfloat162float(hy));
    l23.x = __float2bfloat16_rn(v.z - __bfloat162float(hz));
    l23.y = __float2bfloat16_rn(v.w - __bfloat162float(hw));
    reinterpret_cast<uint2*>(hi)[i] = make_uint2(*reinterpret_cast<uint32_t*>(&h01),
                                                 *reinterpret_cast<uint32_t*>(&h23));
    reinterpret_cast<uint2*>(lo)[i] = make_uint2(*reinterpret_cast<uint32_t*>(&l01),
                                                 *reinterpret_cast<uint32_t*>(&l23));
}

// ---------------------------------------------------------------------------
// bf16-split tensor-core GEMM body: C[.,N] tile (bm,bn) = (Ah+Al) @ (Bh+Bl)^T
// 3 MMAs per fragment pair (hh, hl, lh). CTA 128x128, BK=32, 256 threads,
// 8 warps (2M x 4N), warp tile 64x32. 2-stage cp.async.
// ---------------------------------------------------------------------------
#define BM 128
#define BN 128
#define BKT 32
#define STR 40                     // padded row stride in bf16 elems (80B)
#define GSTAGES 2
#define SELEMS (4 * 128 * STR)     // bf16 elems per stage (Ah,Al,Bh,Bl)
#define GEMM_SMEM (GSTAGES * SELEMS * 2)

__device__ __forceinline__ void mma16816(float* c, const uint32_t* a, const uint32_t* b) {
    asm volatile(
        "mma.sync.aligned.m16n8k16.row.col.f32.bf16.bf16.f32 "
        "{%0,%1,%2,%3}, {%4,%5,%6,%7}, {%8,%9}, {%0,%1,%2,%3};"
        : "+f"(c[0]), "+f"(c[1]), "+f"(c[2]), "+f"(c[3])
        : "r"(a[0]), "r"(a[1]), "r"(a[2]), "r"(a[3]), "r"(b[0]), "r"(b[1]));
}

#define LDSM4(R, addr)                                                        \
    asm volatile("ldmatrix.sync.aligned.m8n8.x4.shared.b16 {%0,%1,%2,%3}, [%4];" \
                 : "=r"((R)[0]), "=r"((R)[1]), "=r"((R)[2]), "=r"((R)[3])      \
                 : "r"(addr))
#define LDSM2(R, addr)                                                        \
    asm volatile("ldmatrix.sync.aligned.m8n8.x2.shared.b16 {%0,%1}, [%2];"     \
                 : "=r"((R)[0]), "=r"((R)[1])                                  \
                 : "r"(addr))

__device__ __forceinline__ void gemm_body(
    uint32_t sbase,
    const __nv_bfloat16* __restrict__ Ah, const __nv_bfloat16* __restrict__ Al,
    const __nv_bfloat16* __restrict__ Bh, const __nv_bfloat16* __restrict__ Bl,
    float* __restrict__ C, int N, int K, int bm, int bn) {
    const int tid  = threadIdx.x;
    const int lane = tid & 31;
    const int warp = tid >> 5;
    const int wm   = warp & 1;
    const int wn   = warp >> 1;
    const int ntile = K / BKT;

    float acc[4][4][4];
#pragma unroll
    for (int i = 0; i < 4; i++)
#pragma unroll
        for (int j = 0; j < 4; j++)
#pragma unroll
            for (int r = 0; r < 4; r++) acc[i][j][r] = 0.f;

    auto issue_stage = [&](int it) {
        const int k0 = it * BKT;
        const uint32_t stb = sbase + (uint32_t)(it % GSTAGES) * SELEMS * 2;
#pragma unroll
        for (int i = 0; i < 8; i++) {
            int c   = tid + i * 256;      // 0..2047
            int arr = c >> 9;             // 0:Ah 1:Al 2:Bh 3:Bl
            int row = (c >> 2) & 127;
            int kc  = c & 3;
            const __nv_bfloat16* g = (arr == 0) ? Ah : (arr == 1) ? Al
                                   : (arr == 2) ? Bh : Bl;
            int grow = ((arr < 2) ? bm : bn) + row;
            const __nv_bfloat16* src = g + (size_t)grow * K + k0 + kc * 8;
            uint32_t dst = stb + (uint32_t)(arr * (128 * STR) + row * STR + kc * 8) * 2;
            asm volatile("cp.async.cg.shared.global [%0], [%1], 16;\n" ::"r"(dst), "l"(src));
        }
        asm volatile("cp.async.commit_group;\n");
    };

    auto compute = [&](int stage) {
        const uint32_t stb = sbase + (uint32_t)stage * SELEMS * 2;
        const uint32_t sAh = stb;
        const uint32_t sAl = stb + 128 * STR * 2;
        const uint32_t sBh = stb + 2 * 128 * STR * 2;
        const uint32_t sBl = stb + 3 * 128 * STR * 2;
#pragma unroll
        for (int kf = 0; kf < 2; kf++) {
            uint32_t bh[4][2], bl[4][2];
            const uint32_t boff =
                2u * ((wn * 32 + (lane & 7)) * STR + kf * 16 + ((lane >> 3) & 1) * 8);
#pragma unroll
            for (int ni = 0; ni < 4; ni++) {
                uint32_t d = boff + 2u * (ni * 8) * STR;
                LDSM2(bh[ni], sBh + d);
                LDSM2(bl[ni], sBl + d);
            }
            const uint32_t aoff =
                2u * ((wm * 64 + (lane & 15)) * STR + kf * 16 + (lane >> 4) * 8);
#pragma unroll
            for (int mi = 0; mi < 4; mi++) {
                uint32_t ah[4], al[4];
                uint32_t d = aoff + 2u * (mi * 16) * STR;
                LDSM4(ah, sAh + d);
                LDSM4(al, sAl + d);
#pragma unroll
                for (int ni = 0; ni < 4; ni++) {
                    mma16816(acc[mi][ni], ah, bh[ni]);
                    mma16816(acc[mi][ni], ah, bl[ni]);
                    mma16816(acc[mi][ni], al, bh[ni]);
                }
            }
        }
    };

    issue_stage(0);
    issue_stage(1);
    for (int it = 0; it < ntile; ++it) {
        if (it + 1 < ntile)
            asm volatile("cp.async.wait_group 1;\n" ::: "memory");
        else
            asm volatile("cp.async.wait_group 0;\n" ::: "memory");
        __syncthreads();
        compute(it % GSTAGES);
        __syncthreads();
        if (it + 2 < ntile) issue_stage(it + 2);
    }

#pragma unroll
    for (int mi = 0; mi < 4; mi++) {
        int row0 = bm + wm * 64 + mi * 16 + (lane >> 2);
#pragma unroll
        for (int ni = 0; ni < 4; ni++) {
            int col = bn + wn * 32 + ni * 8 + (lane & 3) * 2;
            *reinterpret_cast<float2*>(&C[(size_t)row0 * N + col]) =
                make_float2(acc[mi][ni][0], acc[mi][ni][1]);
            *reinterpret_cast<float2*>(&C[(size_t)(row0 + 8) * N + col]) =
                make_float2(acc[mi][ni][2], acc[mi][ni][3]);
        }
    }
}

// ---------------------------------------------------------------------------
// Small projections body: b = H@Wb^T, a = H@Wa^T -> beta, expg (one 256-thr block
// covers 32 tokens).
// ---------------------------------------------------------------------------
__device__ __forceinline__ void smallproj_body(int bid,
                                               const float* __restrict__ H,
                                               const float* __restrict__ Wb,
                                               const float* __restrict__ Wa,
                                               const float* __restrict__ dtb,
                                               const float* __restrict__ Alog) {
    const int tok = bid * 32 + (threadIdx.x >> 3);
    const int j8  = threadIdx.x & 7;
    const float* __restrict__ W =
        (j8 < 4) ? (Wb + (size_t)j8 * 8 * HIDDEN) : (Wa + (size_t)(j8 * 8 - 32) * HIDDEN);
    const float4* __restrict__ h4 = reinterpret_cast<const float4*>(H + (size_t)tok * HIDDEN);

    float acc[8];
#pragma unroll
    for (int j = 0; j < 8; j++) acc[j] = 0.f;

    for (int k4 = 0; k4 < HIDDEN / 4; k4++) {
        float4 h = h4[k4];
#pragma unroll
        for (int j = 0; j < 8; j++) {
            float4 w = reinterpret_cast<const float4*>(W + (size_t)j * HIDDEN)[k4];
            acc[j] += h.x * w.x + h.y * w.y + h.z * w.z + h.w * w.w;
        }
    }

#pragma unroll
    for (int jj = 0; jj < 8; jj++) {
        int j = j8 * 8 + jj;
        float s = acc[jj];
        if (j < 32) {
            g_beta[tok * NUM_V_HEADS + j] = 1.f / (1.f + expf(-s));
        } else {
            int hh = j - 32;
            float xin = s + dtb[hh];
            float sp  = (xin > 20.f) ? xin : log1pf(expf(xin));
            g_expg[tok * NUM_V_HEADS + hh] = expf(-expf(Alog[hh]) * sp);
        }
    }
}

// ---------------------------------------------------------------------------
// Gated delta rule recurrence body (8-way k-split, 256 threads/block).
// Block = (head h, 32-wide dv chunk). Thread (w,l): dv = chunk*32 + w*4 + (l>>3),
// k-range [ (l&7)*16, +16 ). Reductions via shfl_xor 1,2,4.
// ---------------------------------------------------------------------------
struct StepIn8 {
    float4 kb[4];
    float4 qb[4];
    float v, eg, be;
};

__device__ __forceinline__ void rec_load8(int t, int h, const float* qbase,
                                          const float* kbase, const float* vbase,
                                          StepIn8& s) {
    const float4* kp = reinterpret_cast<const float4*>(kbase + (size_t)t * QKV_DIM);
    const float4* qp = reinterpret_cast<const float4*>(qbase + (size_t)t * QKV_DIM);
#pragma unroll
    for (int i = 0; i < 4; i++) s.kb[i] = kp[i];
#pragma unroll
    for (int i = 0; i < 4; i++) s.qb[i] = qp[i];
    s.v  = vbase[(size_t)t * QKV_DIM];
    s.eg = g_expg[t * NUM_V_HEADS + h];
    s.be = g_beta[t * NUM_V_HEADS + h];
}

__device__ __forceinline__ void rec_step8(int t, int h, int dv, int kg,
                                          float (&S)[16], const StepIn8& in) {
    const float scale = 0.0883883476483184405f;   // 128^-0.5
    float kv0 = 0.f, kv1 = 0.f, kv2 = 0.f, kv3 = 0.f;
    {
        float4 k = in.kb[0];
        S[0] *= in.eg; kv0 += k.x * S[0];
        S[1] *= in.eg; kv0 += k.y * S[1];
        S[2] *= in.eg; kv0 += k.z * S[2];
        S[3] *= in.eg; kv0 += k.w * S[3];
    }
    {
        float4 k = in.kb[1];
        S[4] *= in.eg; kv1 += k.x * S[4];
        S[5] *= in.eg; kv1 += k.y * S[5];
        S[6] *= in.eg; kv1 += k.z * S[6];
        S[7] *= in.eg; kv1 += k.w * S[7];
    }
    {
        float4 k = in.kb[2];
        S[8]  *= in.eg; kv2 += k.x * S[8];
        S[9]  *= in.eg; kv2 += k.y * S[9];
        S[10] *= in.eg; kv2 += k.z * S[10];
        S[11] *= in.eg; kv2 += k.w * S[11];
    }
    {
        float4 k = in.kb[3];
        S[12] *= in.eg; kv3 += k.x * S[12];
        S[13] *= in.eg; kv3 += k.y * S[13];
        S[14] *= in.eg; kv3 += k.z * S[14];
        S[15] *= in.eg; kv3 += k.w * S[15];
    }
    float kv = (kv0 + kv1) + (kv2 + kv3);
    kv += __shfl_xor_sync(0xffffffffu, kv, 1);
    kv += __shfl_xor_sync(0xffffffffu, kv, 2);
    kv += __shfl_xor_sync(0xffffffffu, kv, 4);
    float delta = (in.v - kv) * in.be;

    float o0 = 0.f, o1 = 0.f, o2 = 0.f, o3 = 0.f;
    {
        float4 k = in.kb[0], q = in.qb[0];
        S[0] += k.x * delta; o0 += q.x * S[0];
        S[1] += k.y * delta; o0 += q.y * S[1];
        S[2] += k.z * delta; o0 += q.z * S[2];
        S[3] += k.w * delta; o0 += q.w * S[3];
    }
    {
        float4 k = in.kb[1], q = in.qb[1];
        S[4] += k.x * delta; o1 += q.x * S[4];
        S[5] += k.y * delta; o1 += q.y * S[5];
        S[6] += k.z * delta; o1 += q.z * S[6];
        S[7] += k.w * delta; o1 += q.w * S[7];
    }
    {
        float4 k = in.kb[2], q = in.qb[2];
        S[8]  += k.x * delta; o2 += q.x * S[8];
        S[9]  += k.y * delta; o2 += q.y * S[9];
        S[10] += k.z * delta; o2 += q.z * S[10];
        S[11] += k.w * delta; o2 += q.w * S[11];
    }
    {
        float4 k = in.kb[3], q = in.qb[3];
        S[12] += k.x * delta; o3 += q.x * S[12];
        S[13] += k.y * delta; o3 += q.y * S[13];
        S[14] += k.z * delta; o3 += q.z * S[14];
        S[15] += k.w * delta; o3 += q.w * S[15];
    }
    float o = (o0 + o1) + (o2 + o3);
    o += __shfl_xor_sync(0xffffffffu, o, 1);
    o += __shfl_xor_sync(0xffffffffu, o, 2);
    o += __shfl_xor_sync(0xffffffffu, o, 4);
    if (kg == 0) g_o[(size_t)t * VALUE_DIM + h * DV + dv] = o * scale;
}

__device__ __forceinline__ void recurrence_body(int bid) {
    const int h     = bid >> 2;
    const int chunk = bid & 3;
    const int w     = threadIdx.x >> 5;
    const int l     = threadIdx.x & 31;
    const int dv    = chunk * 32 + w * 4 + (l >> 3);
    const int kg    = l & 7;
    const int koff  = kg * 16;
    const int kh    = h >> 1;   // rep = 2

    const float* qbase = g_x + kh * DK + koff;
    const float* kbase = g_x + KEY_DIM + kh * DK + koff;
    const float* vbase = g_x + 2 * KEY_DIM + h * DV + dv;

    float S[16];
#pragma unroll
    for (int i = 0; i < 16; i++) S[i] = 0.f;

    StepIn8 bufA, bufB;
    rec_load8(0, h, qbase, kbase, vbase, bufA);

    for (int t = 0; t < T_TOKENS; t += 2) {
        rec_load8(t + 1, h, qbase, kbase, vbase, bufB);
        rec_step8(t, h, dv, kg, S, bufA);
        if (t + 2 < T_TOKENS) rec_load8(t + 2, h, qbase, kbase, vbase, bufA);
        rec_step8(t + 1, h, dv, kg, S, bufB);
    }
}

// ---------------------------------------------------------------------------
// Fused launches
// ---------------------------------------------------------------------------
// qkv GEMM (2048 CTAs) + small projections (128 blocks, scheduled first)
__global__ __launch_bounds__(256, 2) void qkv_smallproj_kernel(
    const float* __restrict__ H, const float* __restrict__ Wb,
    const float* __restrict__ Wa, const float* __restrict__ dtb,
    const float* __restrict__ Alog) {
    extern __shared__ __nv_bfloat16 smem_dyn[];
    if (blockIdx.x < 128) {
        smallproj_body(blockIdx.x, H, Wb, Wa, dtb, Alog);
    } else {
        const uint32_t sbase = (uint32_t)__cvta_generic_to_shared(smem_dyn);
        int lid = blockIdx.x - 128;
        gemm_body(sbase, g_Hhi, g_Hlo, g_W1hi, g_W1lo, g_mixed,
                  QKV_DIM, HIDDEN, (lid >> 6) * 128, (lid & 63) * 128);
    }
}

// z GEMM (1024 CTAs) + recurrence (128 blocks, scheduled first)
__global__ __launch_bounds__(256, 2) void z_rec_kernel() {
    extern __shared__ __nv_bfloat16 smem_dyn[];
    if (blockIdx.x < 128) {
        recurrence_body(blockIdx.x);
    } else {
        const uint32_t sbase = (uint32_t)__cvta_generic_to_shared(smem_dyn);
        int lid = blockIdx.x - 128;
        gemm_body(sbase, g_Hhi, g_Hlo, g_W2hi, g_W2lo, g_z,
                  VALUE_DIM, HIDDEN, (lid >> 5) * 128, (lid & 31) * 128);
    }
}

// output projection GEMM
__global__ __launch_bounds__(256, 2) void out_gemm_kernel(float* __restrict__ out) {
    extern __shared__ __nv_bfloat16 smem_dyn[];
    const uint32_t sbase = (uint32_t)__cvta_generic_to_shared(smem_dyn);
    gemm_body(sbase, g_Ohi, g_Olo, g_W3hi, g_W3lo, out,
              HIDDEN, VALUE_DIM, blockIdx.y * 128, blockIdx.x * 128);
}

// ---------------------------------------------------------------------------
// Depthwise causal conv1d (K=4) + SiLU. Each thread: 1 channel x 8 timesteps.
// ---------------------------------------------------------------------------
__device__ __forceinline__ float silu_f(float s) { return s / (1.f + expf(-s)); }

__global__ __launch_bounds__(256) void conv_silu_kernel(const float* __restrict__ cw) {
    const int c  = blockIdx.x * 256 + threadIdx.x;
    const int t0 = blockIdx.y * 8;
    const float w0 = cw[c * 4 + 0], w1 = cw[c * 4 + 1];
    const float w2 = cw[c * 4 + 2], w3 = cw[c * 4 + 3];
    float m[11];
#pragma unroll
    for (int i = 0; i < 11; i++) {
        int t = t0 - 3 + i;
        m[i] = (t >= 0) ? g_mixed[(size_t)t * QKV_DIM + c] : 0.f;
    }
#pragma unroll
    for (int j = 0; j < 8; j++) {
        float s = m[j] * w0 + m[j + 1] * w1 + m[j + 2] * w2 + m[j + 3] * w3;
        g_x[(size_t)(t0 + j) * QKV_DIM + c] = silu_f(s);
    }
}

// ---------------------------------------------------------------------------
// In-place L2 normalization of q and k head vectors
// ---------------------------------------------------------------------------
__global__ __launch_bounds__(128) void l2norm_qk_kernel() {
    int t = blockIdx.x;
    int w = threadIdx.x >> 5;
    int l = threadIdx.x & 31;
    for (int hh = w; hh < NUM_K_HEADS; hh += 4) {
#pragma unroll
        for (int which = 0; which < 2; which++) {
            float* base = g_x + (size_t)t * QKV_DIM + which * KEY_DIM + hh * DK;
            float4 v = reinterpret_cast<float4*>(base)[l];
            float ss = v.x * v.x + v.y * v.y + v.z * v.z + v.w * v.w;
#pragma unroll
            for (int o = 16; o >= 1; o >>= 1) ss += __shfl_xor_sync(0xffffffffu, ss, o);
            float r = rsqrtf(ss + 1e-6f);
            v.x *= r; v.y *= r; v.z *= r; v.w *= r;
            reinterpret_cast<float4*>(base)[l] = v;
        }
    }
}

// ---------------------------------------------------------------------------
// Gated RMSNorm; emits bf16 hi/lo split directly (feeds output GEMM)
// ---------------------------------------------------------------------------
__global__ __launch_bounds__(128) void gated_norm_kernel(const float* __restrict__ norm_w) {
    int t = blockIdx.x;
    int w = threadIdx.x >> 5;
    int l = threadIdx.x & 31;
    float4 nw = reinterpret_cast<const float4*>(norm_w)[l];
    for (int h = w; h < NUM_V_HEADS; h += 4) {
        size_t off = (size_t)t * VALUE_DIM + h * DV;
        float4 o4 = reinterpret_cast<float4*>(g_o + off)[l];
        float ss = o4.x * o4.x + o4.y * o4.y + o4.z * o4.z + o4.w * o4.w;
#pragma unroll
        for (int o = 16; o >= 1; o >>= 1) ss += __shfl_xor_sync(0xffffffffu, ss, o);
        float r = rsqrtf(ss * (1.f / DV) + 1e-6f);
        float4 z4 = reinterpret_cast<const float4*>(g_z + off)[l];
        float y0 = o4.x * r * nw.x * silu_f(z4.x);
        float y1 = o4.y * r * nw.y * silu_f(z4.y);
        float y2 = o4.z * r * nw.z * silu_f(z4.z);
        float y3 = o4.w * r * nw.w * silu_f(z4.w);
        __nv_bfloat162 h01, h23, l01, l23;
        h01.x = __float2bfloat16_rn(y0); h01.y = __float2bfloat16_rn(y1);
        h23.x = __float2bfloat16_rn(y2); h23.y = __float2bfloat16_rn(y3);
        l01.x = __float2bfloat16_rn(y0 - __bfloat162float(h01.x));
        l01.y = __float2bfloat16_rn(y1 - __bfloat162float(h01.y));
        l23.x = __float2bfloat16_rn(y2 - __bfloat162float(h23.x));
        l23.y = __float2bfloat16_rn(y3 - __bfloat162float(h23.y));
        reinterpret_cast<uint2*>(g_Ohi + off)[l] =
            make_uint2(*reinterpret_cast<uint32_t*>(&h01), *reinterpret_cast<uint32_t*>(&h23));
        reinterpret_cast<uint2*>(g_Olo + off)[l] =
            make_uint2(*reinterpret_cast<uint32_t*>(&l01), *reinterpret_cast<uint32_t*>(&l23));
    }
}

// ---------------------------------------------------------------------------
// Launch
// ---------------------------------------------------------------------------
extern "C" void kernel_launch(void* const* d_in, const int* in_sizes, int n_in,
                              void* d_out, int out_size) {
    const float* H     = (const float*)d_in[0];
    const float* Wqkv  = (const float*)d_in[1];
    const float* Wz    = (const float*)d_in[2];
    const float* Wb    = (const float*)d_in[3];
    const float* Wa    = (const float*)d_in[4];
    const float* convw = (const float*)d_in[5];
    const float* dtb   = (const float*)d_in[6];
    const float* Alog  = (const float*)d_in[7];
    const float* normw = (const float*)d_in[8];
    const float* Wout  = (const float*)d_in[9];
    float* out = (float*)d_out;

    __nv_bfloat16 *Hhi, *Hlo, *W1hi, *W1lo, *W2hi, *W2lo, *W3hi, *W3lo;
    cudaGetSymbolAddress((void**)&Hhi,  g_Hhi);
    cudaGetSymbolAddress((void**)&Hlo,  g_Hlo);
    cudaGetSymbolAddress((void**)&W1hi, g_W1hi);
    cudaGetSymbolAddress((void**)&W1lo, g_W1lo);
    cudaGetSymbolAddress((void**)&W2hi, g_W2hi);
    cudaGetSymbolAddress((void**)&W2lo, g_W2lo);
    cudaGetSymbolAddress((void**)&W3hi, g_W3hi);
    cudaGetSymbolAddress((void**)&W3lo, g_W3lo);

    cudaFuncSetAttribute(qkv_smallproj_kernel, cudaFuncAttributeMaxDynamicSharedMemorySize,
                         GEMM_SMEM);
    cudaFuncSetAttribute(z_rec_kernel, cudaFuncAttributeMaxDynamicSharedMemorySize,
                         GEMM_SMEM);
    cudaFuncSetAttribute(out_gemm_kernel, cudaFuncAttributeMaxDynamicSharedMemorySize,
                         GEMM_SMEM);

    // Pre-split GEMM operands to bf16 hi/lo
    {
        int n4;
        n4 = T_TOKENS * HIDDEN / 4;
        split_f32_kernel<<<(n4 + 255) / 256, 256>>>(H, Hhi, Hlo, n4);
        n4 = QKV_DIM * HIDDEN / 4;
        split_f32_kernel<<<(n4 + 255) / 256, 256>>>(Wqkv, W1hi, W1lo, n4);
        n4 = VALUE_DIM * HIDDEN / 4;
        split_f32_kernel<<<(n4 + 255) / 256, 256>>>(Wz, W2hi, W2lo, n4);
        n4 = HIDDEN * VALUE_DIM / 4;
        split_f32_kernel<<<(n4 + 255) / 256, 256>>>(Wout, W3hi, W3lo, n4);
    }

    // qkv projection GEMM + fused small projections (beta/expg)
    qkv_smallproj_kernel<<<128 + (QKV_DIM / BN) * (T_TOKENS / BM), 256, GEMM_SMEM>>>(
        H, Wb, Wa, dtb, Alog);

    // Conv + SiLU
    conv_silu_kernel<<<dim3(QKV_DIM / 256, T_TOKENS / 8), 256>>>(convw);

    // l2 norm of q,k (in place)
    l2norm_qk_kernel<<<T_TOKENS, 128>>>();

    // z projection GEMM + fused gated-delta recurrence (independent work)
    z_rec_kernel<<<128 + (VALUE_DIM / BN) * (T_TOKENS / BM), 256, GEMM_SMEM>>>();

    // Gated RMSNorm -> split bf16 output operand
    gated_norm_kernel<<<T_TOKENS, 128>>>(normw);

    // Output projection
    out_gemm_kernel<<<dim3(HIDDEN / BN, T_TOKENS / BM), 256, GEMM_SMEM>>>(out);
}

// round 10
// speedup vs baseline: 1.0598x; 1.0598x over previous
#include <cuda_runtime.h>
#include <cuda_bf16.h>
#include <math.h>
#include <stdint.h>

// ---------------------------------------------------------------------------
// Problem constants (Qwen3.5 MoE GatedDeltaNet, T=4096)
// ---------------------------------------------------------------------------
#define T_TOKENS   4096
#define HIDDEN     2048
#define NUM_K_HEADS 16
#define NUM_V_HEADS 32
#define DK         128
#define DV         128
#define KEY_DIM    (NUM_K_HEADS * DK)          // 2048
#define VALUE_DIM  (NUM_V_HEADS * DV)          // 4096
#define QKV_DIM    (2 * KEY_DIM + VALUE_DIM)   // 8192
#define KCONV      4

// ---------------------------------------------------------------------------
// Scratch (device globals; no allocations allowed)
// ---------------------------------------------------------------------------
__device__ float g_mixed[(size_t)T_TOKENS * QKV_DIM];
__device__ float g_x[(size_t)T_TOKENS * QKV_DIM];
__device__ float g_z[(size_t)T_TOKENS * VALUE_DIM];
__device__ float g_beta[(size_t)T_TOKENS * NUM_V_HEADS];
__device__ float g_expg[(size_t)T_TOKENS * NUM_V_HEADS];
__device__ float g_o[(size_t)T_TOKENS * VALUE_DIM];

// bf16 hi/lo split operands for tensor-core GEMMs
__device__ __nv_bfloat16 g_Hhi[(size_t)T_TOKENS * HIDDEN];
__device__ __nv_bfloat16 g_Hlo[(size_t)T_TOKENS * HIDDEN];
__device__ __nv_bfloat16 g_W1hi[(size_t)QKV_DIM * HIDDEN];
__device__ __nv_bfloat16 g_W1lo[(size_t)QKV_DIM * HIDDEN];
__device__ __nv_bfloat16 g_W2hi[(size_t)VALUE_DIM * HIDDEN];
__device__ __nv_bfloat16 g_W2lo[(size_t)VALUE_DIM * HIDDEN];
__device__ __nv_bfloat16 g_W3hi[(size_t)HIDDEN * VALUE_DIM];
__device__ __nv_bfloat16 g_W3lo[(size_t)HIDDEN * VALUE_DIM];
__device__ __nv_bfloat16 g_Ohi[(size_t)T_TOKENS * VALUE_DIM];
__device__ __nv_bfloat16 g_Olo[(size_t)T_TOKENS * VALUE_DIM];

// ---------------------------------------------------------------------------
// fp32 -> bf16 hi/lo split (elementwise)
// ---------------------------------------------------------------------------
__global__ __launch_bounds__(256) void split_f32_kernel(const float* __restrict__ src,
                                                        __nv_bfloat16* __restrict__ hi,
                                                        __nv_bfloat16* __restrict__ lo,
                                                        int n4) {
    int i = blockIdx.x * blockDim.x + threadIdx.x;
    if (i >= n4) return;
    float4 v = reinterpret_cast<const float4*>(src)[i];
    __nv_bfloat16 hx = __float2bfloat16_rn(v.x);
    __nv_bfloat16 hy = __float2bfloat16_rn(v.y);
    __nv_bfloat16 hz = __float2bfloat16_rn(v.z);
    __nv_bfloat16 hw = __float2bfloat16_rn(v.w);
    __nv_bfloat162 h01; h01.x = hx; h01.y = hy;
    __nv_bfloat162 h23; h23.x = hz; h23.y = hw;
    __nv_bfloat162 l01, l23;
    l01.x = __float2bfloat16_rn(v.x - __bfloat162float(hx));
    l01.y = __float2bfloat16_rn(v.y - __bfloat162float(hy));
    l23.x = __float2bfloat16_rn(v.z - __bfloat162float(hz));
    l23.y = __float2bfloat16_rn(v.w - __bfloat162float(hw));
    reinterpret_cast<uint2*>(hi)[i] = make_uint2(*reinterpret_cast<uint32_t*>(&h01),
                                                 *reinterpret_cast<uint32_t*>(&h23));
    reinterpret_cast<uint2*>(lo)[i] = make_uint2(*reinterpret_cast<uint32_t*>(&l01),
                                                 *reinterpret_cast<uint32_t*>(&l23));
}

// ---------------------------------------------------------------------------
// bf16-split tensor-core GEMM: C[M,N] = (Ah+Al) @ (Bh+Bl)^T.
// 3 MMAs per fragment pair (hh, hl, lh). CTA 128x128, BK=32, 512 threads,
// 16 warps (4M x 4N), warp tile 32x32. LDG.128 -> reg -> STS.128 prefetch
// (avoids the LDGSTS 8-cyc/op issue floor), 2 smem stages, 1 sync per tile.
// Requires M,N % 128 == 0 and K % 64 == 0.
// ---------------------------------------------------------------------------
#define BM 128
#define BN 128
#define BKT 32
#define STR 40                     // padded row stride in bf16 elems (80B)
#define SELEMS (4 * 128 * STR)     // bf16 elems per stage (Ah,Al,Bh,Bl)
#define GEMM_SMEM (2 * SELEMS * 2)

__device__ __forceinline__ void mma16816(float* c, const uint32_t* a, const uint32_t* b) {
    asm volatile(
        "mma.sync.aligned.m16n8k16.row.col.f32.bf16.bf16.f32 "
        "{%0,%1,%2,%3}, {%4,%5,%6,%7}, {%8,%9}, {%0,%1,%2,%3};"
        : "+f"(c[0]), "+f"(c[1]), "+f"(c[2]), "+f"(c[3])
        : "r"(a[0]), "r"(a[1]), "r"(a[2]), "r"(a[3]), "r"(b[0]), "r"(b[1]));
}

#define LDSM4(R, addr)                                                        \
    asm volatile("ldmatrix.sync.aligned.m8n8.x4.shared.b16 {%0,%1,%2,%3}, [%4];" \
                 : "=r"((R)[0]), "=r"((R)[1]), "=r"((R)[2]), "=r"((R)[3])      \
                 : "r"(addr))
#define LDSM2(R, addr)                                                        \
    asm volatile("ldmatrix.sync.aligned.m8n8.x2.shared.b16 {%0,%1}, [%2];"     \
                 : "=r"((R)[0]), "=r"((R)[1])                                  \
                 : "r"(addr))

__global__ __launch_bounds__(512, 1) void gemm_split_bf16(
    const __nv_bfloat16* __restrict__ Ah, const __nv_bfloat16* __restrict__ Al,
    const __nv_bfloat16* __restrict__ Bh, const __nv_bfloat16* __restrict__ Bl,
    float* __restrict__ C, int M, int N, int K) {
    extern __shared__ __nv_bfloat16 smem_dyn[];
    const uint32_t sbase = (uint32_t)__cvta_generic_to_shared(smem_dyn);

    const int tid  = threadIdx.x;
    const int lane = tid & 31;
    const int warp = tid >> 5;   // 0..15
    const int wm   = warp & 3;   // M quarter (32 rows)
    const int wn   = warp >> 2;  // N quarter (32 cols)
    const int bm   = blockIdx.y * BM;
    const int bn   = blockIdx.x * BN;
    const int ntile = K / BKT;

    // Per-thread load map: 4 chunks of 16B. chunk c = tid + i*512 (0..2047)
    // arr = c>>9 (0:Ah 1:Al 2:Bh 3:Bl), row = (c>>2)&127, kc = c&3.
    const __nv_bfloat16* gsrc[4];
    uint32_t sdst[4];
#pragma unroll
    for (int i = 0; i < 4; i++) {
        int c   = tid + i * 512;
        int arr = c >> 9;
        int row = (c >> 2) & 127;
        int kc  = c & 3;
        const __nv_bfloat16* g = (arr == 0) ? Ah : (arr == 1) ? Al
                               : (arr == 2) ? Bh : Bl;
        int grow = ((arr < 2) ? bm : bn) + row;
        gsrc[i] = g + (size_t)grow * K + kc * 8;
        sdst[i] = (uint32_t)(arr * (128 * STR) + row * STR + kc * 8) * 2;
    }

    float acc[2][4][4];
#pragma unroll
    for (int i = 0; i < 2; i++)
#pragma unroll
        for (int j = 0; j < 4; j++)
#pragma unroll
            for (int r = 0; r < 4; r++) acc[i][j][r] = 0.f;

    uint4 buf[4];

    auto load_regs = [&](int it) {
        const int k0 = it * BKT;
#pragma unroll
        for (int i = 0; i < 4; i++)
            buf[i] = *reinterpret_cast<const uint4*>(gsrc[i] + k0);
    };
    auto sts_regs = [&](int it) {
        const uint32_t stb = (uint32_t)(it & 1) * (SELEMS * 2);
        __nv_bfloat16* sm = smem_dyn;
#pragma unroll
        for (int i = 0; i < 4; i++)
            *reinterpret_cast<uint4*>(reinterpret_cast<char*>(sm) + stb + sdst[i]) = buf[i];
    };

    auto compute = [&](int stage) {
        const uint32_t stb = sbase + (uint32_t)stage * SELEMS * 2;
        const uint32_t sAh = stb;
        const uint32_t sAl = stb + 128 * STR * 2;
        const uint32_t sBh = stb + 2 * 128 * STR * 2;
        const uint32_t sBl = stb + 3 * 128 * STR * 2;
#pragma unroll
        for (int kf = 0; kf < 2; kf++) {
            uint32_t bh[4][2], bl[4][2];
            const uint32_t boff =
                2u * ((wn * 32 + (lane & 7)) * STR + kf * 16 + ((lane >> 3) & 1) * 8);
#pragma unroll
            for (int ni = 0; ni < 4; ni++) {
                uint32_t d = boff + 2u * (ni * 8) * STR;
                LDSM2(bh[ni], sBh + d);
                LDSM2(bl[ni], sBl + d);
            }
            const uint32_t aoff =
                2u * ((wm * 32 + (lane & 15)) * STR + kf * 16 + (lane >> 4) * 8);
#pragma unroll
            for (int mi = 0; mi < 2; mi++) {
                uint32_t ah[4], al[4];
                uint32_t d = aoff + 2u * (mi * 16) * STR;
                LDSM4(ah, sAh + d);
                LDSM4(al, sAl + d);
#pragma unroll
                for (int ni = 0; ni < 4; ni++) {
                    mma16816(acc[mi][ni], ah, bh[ni]);
                    mma16816(acc[mi][ni], ah, bl[ni]);
                    mma16816(acc[mi][ni], al, bh[ni]);
                }
            }
        }
    };

    // Prologue: stage 0 to smem; stage 1 resident in regs.
    load_regs(0);
    sts_regs(0);
    load_regs(1);
    __syncthreads();

    for (int it = 0; it < ntile; ++it) {
        compute(it & 1);
        if (it + 1 < ntile) {
            sts_regs(it + 1);                    // regs -> other stage
            if (it + 2 < ntile) load_regs(it + 2);  // prefetch next into regs
        }
        __syncthreads();
    }

    // Epilogue: fragment layout c0:(r,c) c1:(r,c+1) c2:(r+8,c) c3:(r+8,c+1)
#pragma unroll
    for (int mi = 0; mi < 2; mi++) {
        int row0 = bm + wm * 32 + mi * 16 + (lane >> 2);
#pragma unroll
        for (int ni = 0; ni < 4; ni++) {
            int col = bn + wn * 32 + ni * 8 + (lane & 3) * 2;
            *reinterpret_cast<float2*>(&C[(size_t)row0 * N + col]) =
                make_float2(acc[mi][ni][0], acc[mi][ni][1]);
            *reinterpret_cast<float2*>(&C[(size_t)(row0 + 8) * N + col]) =
                make_float2(acc[mi][ni][2], acc[mi][ni][3]);
        }
    }
}

// ---------------------------------------------------------------------------
// Fused small projections: b = H@Wb^T, a = H@Wa^T -> beta, expg
// ---------------------------------------------------------------------------
__global__ __launch_bounds__(256) void smallproj_kernel(const float* __restrict__ H,
                                                        const float* __restrict__ Wb,
                                                        const float* __restrict__ Wa,
                                                        const float* __restrict__ dtb,
                                                        const float* __restrict__ Alog) {
    const int tok = blockIdx.x * 32 + (threadIdx.x >> 3);
    const int j8  = threadIdx.x & 7;
    const float* __restrict__ W =
        (j8 < 4) ? (Wb + (size_t)j8 * 8 * HIDDEN) : (Wa + (size_t)(j8 * 8 - 32) * HIDDEN);
    const float4* __restrict__ h4 = reinterpret_cast<const float4*>(H + (size_t)tok * HIDDEN);

    float acc[8];
#pragma unroll
    for (int j = 0; j < 8; j++) acc[j] = 0.f;

    for (int k4 = 0; k4 < HIDDEN / 4; k4++) {
        float4 h = h4[k4];
#pragma unroll
        for (int j = 0; j < 8; j++) {
            float4 w = reinterpret_cast<const float4*>(W + (size_t)j * HIDDEN)[k4];
            acc[j] += h.x * w.x + h.y * w.y + h.z * w.z + h.w * w.w;
        }
    }

#pragma unroll
    for (int jj = 0; jj < 8; jj++) {
        int j = j8 * 8 + jj;
        float s = acc[jj];
        if (j < 32) {
            g_beta[tok * NUM_V_HEADS + j] = 1.f / (1.f + expf(-s));
        } else {
            int hh = j - 32;
            float xin = s + dtb[hh];
            float sp  = (xin > 20.f) ? xin : log1pf(expf(xin));
            g_expg[tok * NUM_V_HEADS + hh] = expf(-expf(Alog[hh]) * sp);
        }
    }
}

// ---------------------------------------------------------------------------
// Depthwise causal conv1d (K=4) + SiLU. Each thread: 1 channel x 8 timesteps.
// ---------------------------------------------------------------------------
__device__ __forceinline__ float silu_f(float s) { return s / (1.f + expf(-s)); }

__global__ __launch_bounds__(256) void conv_silu_kernel(const float* __restrict__ cw) {
    const int c  = blockIdx.x * 256 + threadIdx.x;
    const int t0 = blockIdx.y * 8;
    const float w0 = cw[c * 4 + 0], w1 = cw[c * 4 + 1];
    const float w2 = cw[c * 4 + 2], w3 = cw[c * 4 + 3];
    float m[11];
#pragma unroll
    for (int i = 0; i < 11; i++) {
        int t = t0 - 3 + i;
        m[i] = (t >= 0) ? g_mixed[(size_t)t * QKV_DIM + c] : 0.f;
    }
#pragma unroll
    for (int j = 0; j < 8; j++) {
        float s = m[j] * w0 + m[j + 1] * w1 + m[j + 2] * w2 + m[j + 3] * w3;
        g_x[(size_t)(t0 + j) * QKV_DIM + c] = silu_f(s);
    }
}

// ---------------------------------------------------------------------------
// In-place L2 normalization of q and k head vectors
// ---------------------------------------------------------------------------
__global__ __launch_bounds__(128) void l2norm_qk_kernel() {
    int t = blockIdx.x;
    int w = threadIdx.x >> 5;
    int l = threadIdx.x & 31;
    for (int hh = w; hh < NUM_K_HEADS; hh += 4) {
#pragma unroll
        for (int which = 0; which < 2; which++) {
            float* base = g_x + (size_t)t * QKV_DIM + which * KEY_DIM + hh * DK;
            float4 v = reinterpret_cast<float4*>(base)[l];
            float ss = v.x * v.x + v.y * v.y + v.z * v.z + v.w * v.w;
#pragma unroll
            for (int o = 16; o >= 1; o >>= 1) ss += __shfl_xor_sync(0xffffffffu, ss, o);
            float r = rsqrtf(ss + 1e-6f);
            v.x *= r; v.y *= r; v.z *= r; v.w *= r;
            reinterpret_cast<float4*>(base)[l] = v;
        }
    }
}

// ---------------------------------------------------------------------------
// Gated delta rule recurrence (sequential over T).
// Grid: 128 blocks = 32 heads x 4 dv-chunks. Block: 128 threads.
// Thread (w,l): dv = chunk*32 + w*8 + (l>>2); k-range [(l&3)*32, +32).
// Reductions split into 8 independent FMA chains (4-deep) for ILP.
// ---------------------------------------------------------------------------
struct StepIn {
    float4 kb[8];
    float4 qb[8];
    float v, eg, be;
};

__device__ __forceinline__ void rec_load(int t, int h, const float* qbase,
                                         const float* kbase, const float* vbase,
                                         StepIn& s) {
    const float4* kp = reinterpret_cast<const float4*>(kbase + (size_t)t * QKV_DIM);
    const float4* qp = reinterpret_cast<const float4*>(qbase + (size_t)t * QKV_DIM);
#pragma unroll
    for (int i = 0; i < 8; i++) s.kb[i] = kp[i];
#pragma unroll
    for (int i = 0; i < 8; i++) s.qb[i] = qp[i];
    s.v  = vbase[(size_t)t * QKV_DIM];
    s.eg = g_expg[t * NUM_V_HEADS + h];
    s.be = g_beta[t * NUM_V_HEADS + h];
}

__device__ __forceinline__ void rec_step(int t, int h, int dv, int kg,
                                         float (&S)[32], const StepIn& in) {
    const float scale = 0.0883883476483184405f;   // 128^-0.5
    const float eg = in.eg;

    // Phase 1: decay + k.S readout, 8 independent chains (one per float4)
    float ka[8];
#pragma unroll
    for (int i = 0; i < 8; i++) {
        float4 k4 = in.kb[i];
        float a, b;
        S[4 * i + 0] *= eg; a = k4.x * S[4 * i + 0];
        S[4 * i + 1] *= eg; b = k4.y * S[4 * i + 1];
        S[4 * i + 2] *= eg; a += k4.z * S[4 * i + 2];
        S[4 * i + 3] *= eg; b += k4.w * S[4 * i + 3];
        ka[i] = a + b;
    }
    float kv = ((ka[0] + ka[1]) + (ka[2] + ka[3])) + ((ka[4] + ka[5]) + (ka[6] + ka[7]));
    kv += __shfl_xor_sync(0xffffffffu, kv, 1);
    kv += __shfl_xor_sync(0xffffffffu, kv, 2);
    float delta = (in.v - kv) * in.be;

    // Phase 2: rank-1 update + q.S readout, 8 independent chains
    float oa[8];
#pragma unroll
    for (int i = 0; i < 8; i++) {
        float4 k4 = in.kb[i];
        float4 q4 = in.qb[i];
        float a, b;
        S[4 * i + 0] += k4.x * delta; a = q4.x * S[4 * i + 0];
        S[4 * i + 1] += k4.y * delta; b = q4.y * S[4 * i + 1];
        S[4 * i + 2] += k4.z * delta; a += q4.z * S[4 * i + 2];
        S[4 * i + 3] += k4.w * delta; b += q4.w * S[4 * i + 3];
        oa[i] = a + b;
    }
    float o = ((oa[0] + oa[1]) + (oa[2] + oa[3])) + ((oa[4] + oa[5]) + (oa[6] + oa[7]));
    o += __shfl_xor_sync(0xffffffffu, o, 1);
    o += __shfl_xor_sync(0xffffffffu, o, 2);
    if (kg == 0) g_o[(size_t)t * VALUE_DIM + h * DV + dv] = o * scale;
}

__global__ __launch_bounds__(128) void recurrence_kernel() {
    const int h     = blockIdx.x >> 2;
    const int chunk = blockIdx.x & 3;
    const int w     = threadIdx.x >> 5;
    const int l     = threadIdx.x & 31;
    const int dv    = chunk * 32 + w * 8 + (l >> 2);
    const int kg    = l & 3;
    const int koff  = kg * 32;
    const int kh    = h >> 1;   // rep = 2

    const float* qbase = g_x + kh * DK + koff;
    const float* kbase = g_x + KEY_DIM + kh * DK + koff;
    const float* vbase = g_x + 2 * KEY_DIM + h * DV + dv;

    float S[32];
#pragma unroll
    for (int i = 0; i < 32; i++) S[i] = 0.f;

    StepIn bufA, bufB;
    rec_load(0, h, qbase, kbase, vbase, bufA);

    for (int t = 0; t < T_TOKENS; t += 2) {
        rec_load(t + 1, h, qbase, kbase, vbase, bufB);
        rec_step(t, h, dv, kg, S, bufA);
        if (t + 2 < T_TOKENS) rec_load(t + 2, h, qbase, kbase, vbase, bufA);
        rec_step(t + 1, h, dv, kg, S, bufB);
    }
}

// ---------------------------------------------------------------------------
// Gated RMSNorm; emits bf16 hi/lo split directly (feeds output GEMM)
// ---------------------------------------------------------------------------
__global__ __launch_bounds__(128) void gated_norm_kernel(const float* __restrict__ norm_w) {
    int t = blockIdx.x;
    int w = threadIdx.x >> 5;
    int l = threadIdx.x & 31;
    float4 nw = reinterpret_cast<const float4*>(norm_w)[l];
    for (int h = w; h < NUM_V_HEADS; h += 4) {
        size_t off = (size_t)t * VALUE_DIM + h * DV;
        float4 o4 = reinterpret_cast<float4*>(g_o + off)[l];
        float ss = o4.x * o4.x + o4.y * o4.y + o4.z * o4.z + o4.w * o4.w;
#pragma unroll
        for (int o = 16; o >= 1; o >>= 1) ss += __shfl_xor_sync(0xffffffffu, ss, o);
        float r = rsqrtf(ss * (1.f / DV) + 1e-6f);
        float4 z4 = reinterpret_cast<const float4*>(g_z + off)[l];
        float y0 = o4.x * r * nw.x * silu_f(z4.x);
        float y1 = o4.y * r * nw.y * silu_f(z4.y);
        float y2 = o4.z * r * nw.z * silu_f(z4.z);
        float y3 = o4.w * r * nw.w * silu_f(z4.w);
        __nv_bfloat162 h01, h23, l01, l23;
        h01.x = __float2bfloat16_rn(y0); h01.y = __float2bfloat16_rn(y1);
        h23.x = __float2bfloat16_rn(y2); h23.y = __float2bfloat16_rn(y3);
        l01.x = __float2bfloat16_rn(y0 - __bfloat162float(h01.x));
        l01.y = __float2bfloat16_rn(y1 - __bfloat162float(h01.y));
        l23.x = __float2bfloat16_rn(y2 - __bfloat162float(h23.x));
        l23.y = __float2bfloat16_rn(y3 - __bfloat162float(h23.y));
        reinterpret_cast<uint2*>(g_Ohi + off)[l] =
            make_uint2(*reinterpret_cast<uint32_t*>(&h01), *reinterpret_cast<uint32_t*>(&h23));
        reinterpret_cast<uint2*>(g_Olo + off)[l] =
            make_uint2(*reinterpret_cast<uint32_t*>(&l01), *reinterpret_cast<uint32_t*>(&l23));
    }
}

// ---------------------------------------------------------------------------
// Launch
// ---------------------------------------------------------------------------
extern "C" void kernel_launch(void* const* d_in, const int* in_sizes, int n_in,
                              void* d_out, int out_size) {
    const float* H     = (const float*)d_in[0];
    const float* Wqkv  = (const float*)d_in[1];
    const float* Wz    = (const float*)d_in[2];
    const float* Wb    = (const float*)d_in[3];
    const float* Wa    = (const float*)d_in[4];
    const float* convw = (const float*)d_in[5];
    const float* dtb   = (const float*)d_in[6];
    const float* Alog  = (const float*)d_in[7];
    const float* normw = (const float*)d_in[8];
    const float* Wout  = (const float*)d_in[9];
    float* out = (float*)d_out;

    float *mixed, *z;
    __nv_bfloat16 *Hhi, *Hlo, *W1hi, *W1lo, *W2hi, *W2lo, *W3hi, *W3lo, *Ohi, *Olo;
    cudaGetSymbolAddress((void**)&mixed, g_mixed);
    cudaGetSymbolAddress((void**)&z,     g_z);
    cudaGetSymbolAddress((void**)&Hhi,  g_Hhi);
    cudaGetSymbolAddress((void**)&Hlo,  g_Hlo);
    cudaGetSymbolAddress((void**)&W1hi, g_W1hi);
    cudaGetSymbolAddress((void**)&W1lo, g_W1lo);
    cudaGetSymbolAddress((void**)&W2hi, g_W2hi);
    cudaGetSymbolAddress((void**)&W2lo, g_W2lo);
    cudaGetSymbolAddress((void**)&W3hi, g_W3hi);
    cudaGetSymbolAddress((void**)&W3lo, g_W3lo);
    cudaGetSymbolAddress((void**)&Ohi,  g_Ohi);
    cudaGetSymbolAddress((void**)&Olo,  g_Olo);

    cudaFuncSetAttribute(gemm_split_bf16, cudaFuncAttributeMaxDynamicSharedMemorySize,
                         GEMM_SMEM);

    // Pre-split GEMM operands to bf16 hi/lo
    {
        int n4;
        n4 = T_TOKENS * HIDDEN / 4;
        split_f32_kernel<<<(n4 + 255) / 256, 256>>>(H, Hhi, Hlo, n4);
        n4 = QKV_DIM * HIDDEN / 4;
        split_f32_kernel<<<(n4 + 255) / 256, 256>>>(Wqkv, W1hi, W1lo, n4);
        n4 = VALUE_DIM * HIDDEN / 4;
        split_f32_kernel<<<(n4 + 255) / 256, 256>>>(Wz, W2hi, W2lo, n4);
        n4 = HIDDEN * VALUE_DIM / 4;
        split_f32_kernel<<<(n4 + 255) / 256, 256>>>(Wout, W3hi, W3lo, n4);
    }

    // Projections
    gemm_split_bf16<<<dim3(QKV_DIM / BN, T_TOKENS / BM), 512, GEMM_SMEM>>>(
        Hhi, Hlo, W1hi, W1lo, mixed, T_TOKENS, QKV_DIM, HIDDEN);
    gemm_split_bf16<<<dim3(VALUE_DIM / BN, T_TOKENS / BM), 512, GEMM_SMEM>>>(
        Hhi, Hlo, W2hi, W2lo, z, T_TOKENS, VALUE_DIM, HIDDEN);

    // Fused b/a projections + beta/expg
    smallproj_kernel<<<T_TOKENS / 32, 256>>>(H, Wb, Wa, dtb, Alog);

    // Conv + SiLU
    conv_silu_kernel<<<dim3(QKV_DIM / 256, T_TOKENS / 8), 256>>>(convw);

    // l2 norm of q,k (in place)
    l2norm_qk_kernel<<<T_TOKENS, 128>>>();

    // Gated delta rule recurrence
    recurrence_kernel<<<NUM_V_HEADS * 4, 128>>>();

    // Gated RMSNorm -> split bf16 output operand
    gated_norm_kernel<<<T_TOKENS, 128>>>(normw);

    // Output projection
    gemm_split_bf16<<<dim3(HIDDEN / BN, T_TOKENS / BM), 512, GEMM_SMEM>>>(
        Ohi, Olo, W3hi, W3lo, out, T_TOKENS, HIDDEN, VALUE_DIM);
}

// round 17
// speedup vs baseline: 1.1661x; 1.1004x over previous
#include <cuda_runtime.h>
#include <cuda_bf16.h>
#include <math.h>
#include <stdint.h>

// ---------------------------------------------------------------------------
// Problem constants (Qwen3.5 MoE GatedDeltaNet, T=4096)
// ---------------------------------------------------------------------------
#define T_TOKENS   4096
#define HIDDEN     2048
#define NUM_K_HEADS 16
#define NUM_V_HEADS 32
#define DK         128
#define DV         128
#define KEY_DIM    (NUM_K_HEADS * DK)          // 2048
#define VALUE_DIM  (NUM_V_HEADS * DV)          // 4096
#define QKV_DIM    (2 * KEY_DIM + VALUE_DIM)   // 8192
#define KCONV      4

// ---------------------------------------------------------------------------
// Scratch (device globals; no allocations allowed)
// ---------------------------------------------------------------------------
__device__ float g_mixed[(size_t)T_TOKENS * QKV_DIM];
__device__ float g_x[(size_t)T_TOKENS * QKV_DIM];
__device__ float g_z[(size_t)T_TOKENS * VALUE_DIM];
__device__ float g_beta[(size_t)T_TOKENS * NUM_V_HEADS];
__device__ float g_expg[(size_t)T_TOKENS * NUM_V_HEADS];
__device__ float g_o[(size_t)T_TOKENS * VALUE_DIM];

// bf16 hi/lo split operands for tensor-core GEMMs
__device__ __nv_bfloat16 g_Hhi[(size_t)T_TOKENS * HIDDEN];
__device__ __nv_bfloat16 g_Hlo[(size_t)T_TOKENS * HIDDEN];
__device__ __nv_bfloat16 g_W1hi[(size_t)QKV_DIM * HIDDEN];
__device__ __nv_bfloat16 g_W1lo[(size_t)QKV_DIM * HIDDEN];
__device__ __nv_bfloat16 g_W2hi[(size_t)VALUE_DIM * HIDDEN];
__device__ __nv_bfloat16 g_W2lo[(size_t)VALUE_DIM * HIDDEN];
__device__ __nv_bfloat16 g_W3hi[(size_t)HIDDEN * VALUE_DIM];
__device__ __nv_bfloat16 g_W3lo[(size_t)HIDDEN * VALUE_DIM];
__device__ __nv_bfloat16 g_Ohi[(size_t)T_TOKENS * VALUE_DIM];
__device__ __nv_bfloat16 g_Olo[(size_t)T_TOKENS * VALUE_DIM];

// ---------------------------------------------------------------------------
// fp32 -> bf16 hi/lo split (elementwise)
// ---------------------------------------------------------------------------
__global__ __launch_bounds__(256) void split_f32_kernel(const float* __restrict__ src,
                                                        __nv_bfloat16* __restrict__ hi,
                                                        __nv_bfloat16* __restrict__ lo,
                                                        int n4) {
    int i = blockIdx.x * blockDim.x + threadIdx.x;
    if (i >= n4) return;
    float4 v = reinterpret_cast<const float4*>(src)[i];
    __nv_bfloat16 hx = __float2bfloat16_rn(v.x);
    __nv_bfloat16 hy = __float2bfloat16_rn(v.y);
    __nv_bfloat16 hz = __float2bfloat16_rn(v.z);
    __nv_bfloat16 hw = __float2bfloat16_rn(v.w);
    __nv_bfloat162 h01; h01.x = hx; h01.y = hy;
    __nv_bfloat162 h23; h23.x = hz; h23.y = hw;
    __nv_bfloat162 l01, l23;
    l01.x = __float2bfloat16_rn(v.x - __bfloat162float(hx));
    l01.y = __float2bfloat16_rn(v.y - __bfloat162float(hy));
    l23.x = __float2bfloat16_rn(v.z - __bfloat162float(hz));
    l23.y = __float2bfloat16_rn(v.w - __bfloat162float(hw));
    reinterpret_cast<uint2*>(hi)[i] = make_uint2(*reinterpret_cast<uint32_t*>(&h01),
                                                 *reinterpret_cast<uint32_t*>(&h23));
    reinterpret_cast<uint2*>(lo)[i] = make_uint2(*reinterpret_cast<uint32_t*>(&l01),
                                                 *reinterpret_cast<uint32_t*>(&l23));
}

// ---------------------------------------------------------------------------
// Pipelined bf16-split tensor-core GEMM (measured-best config, R5):
// C[M,N] = (Ah+Al) @ (Bh+Bl)^T. 3 MMAs per fragment pair (hh, hl, lh).
// CTA 128x128, BK=32, 256 threads, 8 warps (2M x 4N), warp tile 64x32.
// 2-stage cp.async, 2 CTAs/SM. Requires M,N % 128 == 0 and K % 32 == 0.
// ---------------------------------------------------------------------------
#define BM 128
#define BN 128
#define BKT 32
#define STR 40                     // padded row stride in bf16 elems (80B)
#define GSTAGES 2
#define SELEMS (4 * 128 * STR)     // bf16 elems per stage (Ah,Al,Bh,Bl)
#define GEMM_SMEM (GSTAGES * SELEMS * 2)

__device__ __forceinline__ void mma16816(float* c, const uint32_t* a, const uint32_t* b) {
    asm volatile(
        "mma.sync.aligned.m16n8k16.row.col.f32.bf16.bf16.f32 "
        "{%0,%1,%2,%3}, {%4,%5,%6,%7}, {%8,%9}, {%0,%1,%2,%3};"
        : "+f"(c[0]), "+f"(c[1]), "+f"(c[2]), "+f"(c[3])
        : "r"(a[0]), "r"(a[1]), "r"(a[2]), "r"(a[3]), "r"(b[0]), "r"(b[1]));
}

#define LDSM4(R, addr)                                                        \
    asm volatile("ldmatrix.sync.aligned.m8n8.x4.shared.b16 {%0,%1,%2,%3}, [%4];" \
                 : "=r"((R)[0]), "=r"((R)[1]), "=r"((R)[2]), "=r"((R)[3])      \
                 : "r"(addr))
#define LDSM2(R, addr)                                                        \
    asm volatile("ldmatrix.sync.aligned.m8n8.x2.shared.b16 {%0,%1}, [%2];"     \
                 : "=r"((R)[0]), "=r"((R)[1])                                  \
                 : "r"(addr))

__global__ __launch_bounds__(256, 2) void gemm_split_bf16(
    const __nv_bfloat16* __restrict__ Ah, const __nv_bfloat16* __restrict__ Al,
    const __nv_bfloat16* __restrict__ Bh, const __nv_bfloat16* __restrict__ Bl,
    float* __restrict__ C, int M, int N, int K) {
    extern __shared__ __nv_bfloat16 smem_dyn[];
    const uint32_t sbase = (uint32_t)__cvta_generic_to_shared(smem_dyn);

    const int tid  = threadIdx.x;
    const int lane = tid & 31;
    const int warp = tid >> 5;
    const int wm   = warp & 1;
    const int wn   = warp >> 1;
    const int bm   = blockIdx.y * BM;
    const int bn   = blockIdx.x * BN;
    const int ntile = K / BKT;

    float acc[4][4][4];
#pragma unroll
    for (int i = 0; i < 4; i++)
#pragma unroll
        for (int j = 0; j < 4; j++)
#pragma unroll
            for (int r = 0; r < 4; r++) acc[i][j][r] = 0.f;

    auto issue_stage = [&](int it) {
        const int k0 = it * BKT;
        const uint32_t stb = sbase + (uint32_t)(it % GSTAGES) * SELEMS * 2;
#pragma unroll
        for (int i = 0; i < 8; i++) {
            int c   = tid + i * 256;      // 0..2047
            int arr = c >> 9;             // 0:Ah 1:Al 2:Bh 3:Bl
            int row = (c >> 2) & 127;
            int kc  = c & 3;
            const __nv_bfloat16* g = (arr == 0) ? Ah : (arr == 1) ? Al
                                   : (arr == 2) ? Bh : Bl;
            int grow = ((arr < 2) ? bm : bn) + row;
            const __nv_bfloat16* src = g + (size_t)grow * K + k0 + kc * 8;
            uint32_t dst = stb + (uint32_t)(arr * (128 * STR) + row * STR + kc * 8) * 2;
            asm volatile("cp.async.cg.shared.global [%0], [%1], 16;\n" ::"r"(dst), "l"(src));
        }
        asm volatile("cp.async.commit_group;\n");
    };

    auto compute = [&](int stage) {
        const uint32_t stb = sbase + (uint32_t)stage * SELEMS * 2;
        const uint32_t sAh = stb;
        const uint32_t sAl = stb + 128 * STR * 2;
        const uint32_t sBh = stb + 2 * 128 * STR * 2;
        const uint32_t sBl = stb + 3 * 128 * STR * 2;
#pragma unroll
        for (int kf = 0; kf < 2; kf++) {
            uint32_t bh[4][2], bl[4][2];
            const uint32_t boff =
                2u * ((wn * 32 + (lane & 7)) * STR + kf * 16 + ((lane >> 3) & 1) * 8);
#pragma unroll
            for (int ni = 0; ni < 4; ni++) {
                uint32_t d = boff + 2u * (ni * 8) * STR;
                LDSM2(bh[ni], sBh + d);
                LDSM2(bl[ni], sBl + d);
            }
            const uint32_t aoff =
                2u * ((wm * 64 + (lane & 15)) * STR + kf * 16 + (lane >> 4) * 8);
#pragma unroll
            for (int mi = 0; mi < 4; mi++) {
                uint32_t ah[4], al[4];
                uint32_t d = aoff + 2u * (mi * 16) * STR;
                LDSM4(ah, sAh + d);
                LDSM4(al, sAl + d);
#pragma unroll
                for (int ni = 0; ni < 4; ni++) {
                    mma16816(acc[mi][ni], ah, bh[ni]);
                    mma16816(acc[mi][ni], ah, bl[ni]);
                    mma16816(acc[mi][ni], al, bh[ni]);
                }
            }
        }
    };

    issue_stage(0);
    issue_stage(1);
    for (int it = 0; it < ntile; ++it) {
        if (it + 1 < ntile)
            asm volatile("cp.async.wait_group 1;\n" ::: "memory");
        else
            asm volatile("cp.async.wait_group 0;\n" ::: "memory");
        __syncthreads();
        compute(it % GSTAGES);
        __syncthreads();
        if (it + 2 < ntile) issue_stage(it + 2);
    }

#pragma unroll
    for (int mi = 0; mi < 4; mi++) {
        int row0 = bm + wm * 64 + mi * 16 + (lane >> 2);
#pragma unroll
        for (int ni = 0; ni < 4; ni++) {
            int col = bn + wn * 32 + ni * 8 + (lane & 3) * 2;
            *reinterpret_cast<float2*>(&C[(size_t)row0 * N + col]) =
                make_float2(acc[mi][ni][0], acc[mi][ni][1]);
            *reinterpret_cast<float2*>(&C[(size_t)(row0 + 8) * N + col]) =
                make_float2(acc[mi][ni][2], acc[mi][ni][3]);
        }
    }
}

// ---------------------------------------------------------------------------
// Fused small projections: b = H@Wb^T, a = H@Wa^T -> beta, expg
// ---------------------------------------------------------------------------
__global__ __launch_bounds__(256) void smallproj_kernel(const float* __restrict__ H,
                                                        const float* __restrict__ Wb,
                                                        const float* __restrict__ Wa,
                                                        const float* __restrict__ dtb,
                                                        const float* __restrict__ Alog) {
    const int tok = blockIdx.x * 32 + (threadIdx.x >> 3);
    const int j8  = threadIdx.x & 7;
    const float* __restrict__ W =
        (j8 < 4) ? (Wb + (size_t)j8 * 8 * HIDDEN) : (Wa + (size_t)(j8 * 8 - 32) * HIDDEN);
    const float4* __restrict__ h4 = reinterpret_cast<const float4*>(H + (size_t)tok * HIDDEN);

    float acc[8];
#pragma unroll
    for (int j = 0; j < 8; j++) acc[j] = 0.f;

    for (int k4 = 0; k4 < HIDDEN / 4; k4++) {
        float4 h = h4[k4];
#pragma unroll
        for (int j = 0; j < 8; j++) {
            float4 w = reinterpret_cast<const float4*>(W + (size_t)j * HIDDEN)[k4];
            acc[j] += h.x * w.x + h.y * w.y + h.z * w.z + h.w * w.w;
        }
    }

#pragma unroll
    for (int jj = 0; jj < 8; jj++) {
        int j = j8 * 8 + jj;
        float s = acc[jj];
        if (j < 32) {
            g_beta[tok * NUM_V_HEADS + j] = 1.f / (1.f + expf(-s));
        } else {
            int hh = j - 32;
            float xin = s + dtb[hh];
            float sp  = (xin > 20.f) ? xin : log1pf(expf(xin));
            g_expg[tok * NUM_V_HEADS + hh] = expf(-expf(Alog[hh]) * sp);
        }
    }
}

// ---------------------------------------------------------------------------
// Depthwise causal conv1d (K=4) + SiLU. Each thread: 1 channel x 8 timesteps.
// ---------------------------------------------------------------------------
__device__ __forceinline__ float silu_f(float s) { return s / (1.f + expf(-s)); }

__global__ __launch_bounds__(256) void conv_silu_kernel(const float* __restrict__ cw) {
    const int c  = blockIdx.x * 256 + threadIdx.x;
    const int t0 = blockIdx.y * 8;
    const float w0 = cw[c * 4 + 0], w1 = cw[c * 4 + 1];
    const float w2 = cw[c * 4 + 2], w3 = cw[c * 4 + 3];
    float m[11];
#pragma unroll
    for (int i = 0; i < 11; i++) {
        int t = t0 - 3 + i;
        m[i] = (t >= 0) ? g_mixed[(size_t)t * QKV_DIM + c] : 0.f;
    }
#pragma unroll
    for (int j = 0; j < 8; j++) {
        float s = m[j] * w0 + m[j + 1] * w1 + m[j + 2] * w2 + m[j + 3] * w3;
        g_x[(size_t)(t0 + j) * QKV_DIM + c] = silu_f(s);
    }
}

// ---------------------------------------------------------------------------
// In-place L2 normalization of q and k head vectors
// ---------------------------------------------------------------------------
__global__ __launch_bounds__(128) void l2norm_qk_kernel() {
    int t = blockIdx.x;
    int w = threadIdx.x >> 5;
    int l = threadIdx.x & 31;
    for (int hh = w; hh < NUM_K_HEADS; hh += 4) {
#pragma unroll
        for (int which = 0; which < 2; which++) {
            float* base = g_x + (size_t)t * QKV_DIM + which * KEY_DIM + hh * DK;
            float4 v = reinterpret_cast<float4*>(base)[l];
            float ss = v.x * v.x + v.y * v.y + v.z * v.z + v.w * v.w;
#pragma unroll
            for (int o = 16; o >= 1; o >>= 1) ss += __shfl_xor_sync(0xffffffffu, ss, o);
            float r = rsqrtf(ss + 1e-6f);
            v.x *= r; v.y *= r; v.z *= r; v.w *= r;
            reinterpret_cast<float4*>(base)[l] = v;
        }
    }
}

// ---------------------------------------------------------------------------
// Gated delta rule recurrence (sequential over T).
// Grid: 128 blocks = 32 heads x 4 dv-chunks. Block: 256 threads (8 warps,
// 2 warps/SMSP for issue overlap). Thread (w,l): dv = chunk*32 + w*4 + (l>>3),
// k-range [(l&7)*16, +16). Reductions: 4 independent FMA chains + shfl 1,2,4.
// ---------------------------------------------------------------------------
struct StepIn8 {
    float4 kb[4];
    float4 qb[4];
    float v, eg, be;
};

__device__ __forceinline__ void rec_load8(int t, int h, const float* qbase,
                                          const float* kbase, const float* vbase,
                                          StepIn8& s) {
    const float4* kp = reinterpret_cast<const float4*>(kbase + (size_t)t * QKV_DIM);
    const float4* qp = reinterpret_cast<const float4*>(qbase + (size_t)t * QKV_DIM);
#pragma unroll
    for (int i = 0; i < 4; i++) s.kb[i] = kp[i];
#pragma unroll
    for (int i = 0; i < 4; i++) s.qb[i] = qp[i];
    s.v  = vbase[(size_t)t * QKV_DIM];
    s.eg = g_expg[t * NUM_V_HEADS + h];
    s.be = g_beta[t * NUM_V_HEADS + h];
}

__device__ __forceinline__ void rec_step8(int t, int h, int dv, int kg,
                                          float (&S)[16], const StepIn8& in) {
    const float scale = 0.0883883476483184405f;   // 128^-0.5
    const float eg = in.eg;

    // Phase 1: decay + k.S readout, 4 independent chains (one per float4)
    float ka[4];
#pragma unroll
    for (int i = 0; i < 4; i++) {
        float4 k4 = in.kb[i];
        float a, b;
        S[4 * i + 0] *= eg; a = k4.x * S[4 * i + 0];
        S[4 * i + 1] *= eg; b = k4.y * S[4 * i + 1];
        S[4 * i + 2] *= eg; a += k4.z * S[4 * i + 2];
        S[4 * i + 3] *= eg; b += k4.w * S[4 * i + 3];
        ka[i] = a + b;
    }
    float kv = (ka[0] + ka[1]) + (ka[2] + ka[3]);
    kv += __shfl_xor_sync(0xffffffffu, kv, 1);
    kv += __shfl_xor_sync(0xffffffffu, kv, 2);
    kv += __shfl_xor_sync(0xffffffffu, kv, 4);
    float delta = (in.v - kv) * in.be;

    // Phase 2: rank-1 update + q.S readout, 4 independent chains
    float oa[4];
#pragma unroll
    for (int i = 0; i < 4; i++) {
        float4 k4 = in.kb[i];
        float4 q4 = in.qb[i];
        float a, b;
        S[4 * i + 0] += k4.x * delta; a = q4.x * S[4 * i + 0];
        S[4 * i + 1] += k4.y * delta; b = q4.y * S[4 * i + 1];
        S[4 * i + 2] += k4.z * delta; a += q4.z * S[4 * i + 2];
        S[4 * i + 3] += k4.w * delta; b += q4.w * S[4 * i + 3];
        oa[i] = a + b;
    }
    float o = (oa[0] + oa[1]) + (oa[2] + oa[3]);
    o += __shfl_xor_sync(0xffffffffu, o, 1);
    o += __shfl_xor_sync(0xffffffffu, o, 2);
    o += __shfl_xor_sync(0xffffffffu, o, 4);
    if (kg == 0) g_o[(size_t)t * VALUE_DIM + h * DV + dv] = o * scale;
}

__global__ __launch_bounds__(256) void recurrence_kernel() {
    const int h     = blockIdx.x >> 2;
    const int chunk = blockIdx.x & 3;
    const int w     = threadIdx.x >> 5;   // 0..7
    const int l     = threadIdx.x & 31;
    const int dv    = chunk * 32 + w * 4 + (l >> 3);
    const int kg    = l & 7;
    const int koff  = kg * 16;
    const int kh    = h >> 1;   // rep = 2

    const float* qbase = g_x + kh * DK + koff;
    const float* kbase = g_x + KEY_DIM + kh * DK + koff;
    const float* vbase = g_x + 2 * KEY_DIM + h * DV + dv;

    float S[16];
#pragma unroll
    for (int i = 0; i < 16; i++) S[i] = 0.f;

    StepIn8 bufA, bufB;
    rec_load8(0, h, qbase, kbase, vbase, bufA);

    for (int t = 0; t < T_TOKENS; t += 2) {
        rec_load8(t + 1, h, qbase, kbase, vbase, bufB);
        rec_step8(t, h, dv, kg, S, bufA);
        if (t + 2 < T_TOKENS) rec_load8(t + 2, h, qbase, kbase, vbase, bufA);
        rec_step8(t + 1, h, dv, kg, S, bufB);
    }
}

// ---------------------------------------------------------------------------
// Gated RMSNorm; emits bf16 hi/lo split directly (feeds output GEMM)
// ---------------------------------------------------------------------------
__global__ __launch_bounds__(128) void gated_norm_kernel(const float* __restrict__ norm_w) {
    int t = blockIdx.x;
    int w = threadIdx.x >> 5;
    int l = threadIdx.x & 31;
    float4 nw = reinterpret_cast<const float4*>(norm_w)[l];
    for (int h = w; h < NUM_V_HEADS; h += 4) {
        size_t off = (size_t)t * VALUE_DIM + h * DV;
        float4 o4 = reinterpret_cast<float4*>(g_o + off)[l];
        float ss = o4.x * o4.x + o4.y * o4.y + o4.z * o4.z + o4.w * o4.w;
#pragma unroll
        for (int o = 16; o >= 1; o >>= 1) ss += __shfl_xor_sync(0xffffffffu, ss, o);
        float r = rsqrtf(ss * (1.f / DV) + 1e-6f);
        float4 z4 = reinterpret_cast<const float4*>(g_z + off)[l];
        float y0 = o4.x * r * nw.x * silu_f(z4.x);
        float y1 = o4.y * r * nw.y * silu_f(z4.y);
        float y2 = o4.z * r * nw.z * silu_f(z4.z);
        float y3 = o4.w * r * nw.w * silu_f(z4.w);
        __nv_bfloat162 h01, h23, l01, l23;
        h01.x = __float2bfloat16_rn(y0); h01.y = __float2bfloat16_rn(y1);
        h23.x = __float2bfloat16_rn(y2); h23.y = __float2bfloat16_rn(y3);
        l01.x = __float2bfloat16_rn(y0 - __bfloat162float(h01.x));
        l01.y = __float2bfloat16_rn(y1 - __bfloat162float(h01.y));
        l23.x = __float2bfloat16_rn(y2 - __bfloat162float(h23.x));
        l23.y = __float2bfloat16_rn(y3 - __bfloat162float(h23.y));
        reinterpret_cast<uint2*>(g_Ohi + off)[l] =
            make_uint2(*reinterpret_cast<uint32_t*>(&h01), *reinterpret_cast<uint32_t*>(&h23));
        reinterpret_cast<uint2*>(g_Olo + off)[l] =
            make_uint2(*reinterpret_cast<uint32_t*>(&l01), *reinterpret_cast<uint32_t*>(&l23));
    }
}

// ---------------------------------------------------------------------------
// Launch
// ---------------------------------------------------------------------------
extern "C" void kernel_launch(void* const* d_in, const int* in_sizes, int n_in,
                              void* d_out, int out_size) {
    const float* H     = (const float*)d_in[0];
    const float* Wqkv  = (const float*)d_in[1];
    const float* Wz    = (const float*)d_in[2];
    const float* Wb    = (const float*)d_in[3];
    const float* Wa    = (const float*)d_in[4];
    const float* convw = (const float*)d_in[5];
    const float* dtb   = (const float*)d_in[6];
    const float* Alog  = (const float*)d_in[7];
    const float* normw = (const float*)d_in[8];
    const float* Wout  = (const float*)d_in[9];
    float* out = (float*)d_out;

    float *mixed, *z;
    __nv_bfloat16 *Hhi, *Hlo, *W1hi, *W1lo, *W2hi, *W2lo, *W3hi, *W3lo, *Ohi, *Olo;
    cudaGetSymbolAddress((void**)&mixed, g_mixed);
    cudaGetSymbolAddress((void**)&z,     g_z);
    cudaGetSymbolAddress((void**)&Hhi,  g_Hhi);
    cudaGetSymbolAddress((void**)&Hlo,  g_Hlo);
    cudaGetSymbolAddress((void**)&W1hi, g_W1hi);
    cudaGetSymbolAddress((void**)&W1lo, g_W1lo);
    cudaGetSymbolAddress((void**)&W2hi, g_W2hi);
    cudaGetSymbolAddress((void**)&W2lo, g_W2lo);
    cudaGetSymbolAddress((void**)&W3hi, g_W3hi);
    cudaGetSymbolAddress((void**)&W3lo, g_W3lo);
    cudaGetSymbolAddress((void**)&Ohi,  g_Ohi);
    cudaGetSymbolAddress((void**)&Olo,  g_Olo);

    cudaFuncSetAttribute(gemm_split_bf16, cudaFuncAttributeMaxDynamicSharedMemorySize,
                         GEMM_SMEM);

    // Pre-split GEMM operands to bf16 hi/lo
    {
        int n4;
        n4 = T_TOKENS * HIDDEN / 4;
        split_f32_kernel<<<(n4 + 255) / 256, 256>>>(H, Hhi, Hlo, n4);
        n4 = QKV_DIM * HIDDEN / 4;
        split_f32_kernel<<<(n4 + 255) / 256, 256>>>(Wqkv, W1hi, W1lo, n4);
        n4 = VALUE_DIM * HIDDEN / 4;
        split_f32_kernel<<<(n4 + 255) / 256, 256>>>(Wz, W2hi, W2lo, n4);
        n4 = HIDDEN * VALUE_DIM / 4;
        split_f32_kernel<<<(n4 + 255) / 256, 256>>>(Wout, W3hi, W3lo, n4);
    }

    // Projections
    gemm_split_bf16<<<dim3(QKV_DIM / BN, T_TOKENS / BM), 256, GEMM_SMEM>>>(
        Hhi, Hlo, W1hi, W1lo, mixed, T_TOKENS, QKV_DIM, HIDDEN);
    gemm_split_bf16<<<dim3(VALUE_DIM / BN, T_TOKENS / BM), 256, GEMM_SMEM>>>(
        Hhi, Hlo, W2hi, W2lo, z, T_TOKENS, VALUE_DIM, HIDDEN);

    // Fused b/a projections + beta/expg
    smallproj_kernel<<<T_TOKENS / 32, 256>>>(H, Wb, Wa, dtb, Alog);

    // Conv + SiLU
    conv_silu_kernel<<<dim3(QKV_DIM / 256, T_TOKENS / 8), 256>>>(convw);

    // l2 norm of q,k (in place)
    l2norm_qk_kernel<<<T_TOKENS, 128>>>();

    // Gated delta rule recurrence (256 threads: 2 warps/SMSP for issue overlap)
    recurrence_kernel<<<NUM_V_HEADS * 4, 256>>>();

    // Gated RMSNorm -> split bf16 output operand
    gated_norm_kernel<<<T_TOKENS, 128>>>(normw);

    // Output projection
    gemm_split_bf16<<<dim3(HIDDEN / BN, T_TOKENS / BM), 256, GEMM_SMEM>>>(
        Ohi, Olo, W3hi, W3lo, out, T_TOKENS, HIDDEN, VALUE_DIM);
}